// round 2
// baseline (speedup 1.0000x reference)
#include <cuda_runtime.h>

// ---------------- problem constants ----------------
#define BATCH   16
#define TSEQ    16384
#define CIN     8
#define CHUNK   32
#define GRANGES 64          // ranges per batch
#define LSTEPS  256         // TSEQ / GRANGES, multiple of CHUNK
#define SIGLEN  819         // 9 + 81 + 729
#define HID     256

// ---------------- scratch (no allocations allowed) ----------------
__device__ float  g_part[BATCH * GRANGES * SIGLEN];   // fp32 range signatures
__device__ double g_dbuf[BATCH * 63 * SIGLEN];        // fp64 tree ping-pong slots

// =====================================================================
// Kernel 1: per-range truncated signature (levels 1..3), fp32.
// Grid (GRANGES, BATCH), 96 threads (81 active in main loop).
// Thread (i,j) owns S2[i][j] and S3[i][j][0..8]; S1[i] kept privately.
// Per step (Chen):  S3 += S2(old)⊗d + S1(old)⊗(d⊗d)/2 + d⊗d⊗d/6
//                   S2 += S1(old)⊗d + d⊗d/2 ;  S1 += d
// Folded:  S3[ijk] += (S2ij + 0.5*(S1i + di/3)*dj) * dk
//          S2ij    += (S1i + 0.5*di) * dj
// =====================================================================
__global__ __launch_bounds__(96)
void sig_partial_kernel(const float* __restrict__ x)
{
    __shared__ __align__(16) float ds[LSTEPS * 8];   // increments, 8 spatial channels (time = const 1/32)

    const int b = blockIdx.y;
    const int g = blockIdx.x;
    const int tid = threadIdx.x;
    const float DT = 1.0f / 32.0f;

    // stage increments into shared (chunk-aligned ranges: first step of each
    // 32-chunk jumps from the zero basepoint, i.e. prev = 0)
    const long base = ((long)b * TSEQ + (long)g * LSTEPS) * CIN;
    for (int idx = tid; idx < LSTEPS * 8; idx += 96) {
        int s = idx >> 3, c = idx & 7;
        float cur  = x[base + (long)s * CIN + c];
        float prev = (s & 31) ? x[base + (long)(s - 1) * CIN + c] : 0.0f;
        ds[idx] = cur - prev;
    }
    __syncthreads();

    if (tid < 81) {
        const int i = tid / 9;
        const int j = tid % 9;
        float s1i = 0.0f, s2 = 0.0f;
        float s3[9];
        #pragma unroll
        for (int k = 0; k < 9; ++k) s3[k] = 0.0f;

        const float* dp = ds;
        #pragma unroll 2
        for (int s = 0; s < LSTEPS; ++s, dp += 8) {
            float di = (i < 8) ? dp[i] : DT;
            float dj = (j < 8) ? dp[j] : DT;
            float4 dlo = *reinterpret_cast<const float4*>(dp);
            float4 dhi = *reinterpret_cast<const float4*>(dp + 4);

            float a = fmaf(fmaf(di, (1.0f / 3.0f), s1i), 0.5f * dj, s2);
            s3[0] = fmaf(a, dlo.x, s3[0]);
            s3[1] = fmaf(a, dlo.y, s3[1]);
            s3[2] = fmaf(a, dlo.z, s3[2]);
            s3[3] = fmaf(a, dlo.w, s3[3]);
            s3[4] = fmaf(a, dhi.x, s3[4]);
            s3[5] = fmaf(a, dhi.y, s3[5]);
            s3[6] = fmaf(a, dhi.z, s3[6]);
            s3[7] = fmaf(a, dhi.w, s3[7]);
            s3[8] = fmaf(a, DT,    s3[8]);

            s2  = fmaf(fmaf(di, 0.5f, s1i), dj, s2);
            s1i += di;
        }

        float* out = g_part + (long)(b * GRANGES + g) * SIGLEN;
        if (j == 0) out[i] = s1i;
        out[9 + tid] = s2;
        float* o3 = out + 90 + tid * 9;
        #pragma unroll
        for (int k = 0; k < 9; ++k) o3[k] = s3[k];
    }
}

// =====================================================================
// Kernel 2: per-batch fp64 tree combine (group product), log3, MLP.
// One block per batch, 1024 threads. 12 groups of 81 threads do combines.
// Group product: c1 = a1+b1 ; c2 = a2+b2+a1⊗b1 ; c3 = a3+b3+a1⊗b2+a2⊗b1
// (a = earlier/left range — order matters, tensor product is non-commutative)
// =====================================================================
__global__ __launch_bounds__(1024)
void combine_mlp_kernel(const float* __restrict__ W1, const float* __restrict__ b1v,
                        const float* __restrict__ W2, const float* __restrict__ b2v,
                        float* __restrict__ out)
{
    __shared__ float flat_sh[SIGLEN];
    __shared__ __align__(16) float hred[8][HID];
    __shared__ float osum[8];

    const int b   = blockIdx.x;
    const int tid = threadIdx.x;
    const int grp    = tid / 81;     // 0..12 ; groups 0..11 active in tree
    const int lane81 = tid % 81;
    const int i = lane81 / 9;
    const int j = lane81 % 9;

    const float* fpart = g_part + (long)b * GRANGES * SIGLEN;
    double*      dbuf  = g_dbuf + (long)b * 63 * SIGLEN;

    // ---- level 0: 32 combines, float inputs -> double outputs (slots 0..31)
    if (grp < 12) {
        for (int q = grp; q < 32; q += 12) {
            const float* A = fpart + (long)(2 * q)     * SIGLEN;
            const float* B = fpart + (long)(2 * q + 1) * SIGLEN;
            double*      C = dbuf  + (long)q * SIGLEN;
            double a1i  = (double)A[i];
            double b1j  = (double)B[j];
            double a2ij = (double)A[9 + lane81];
            if (j == 0) C[i] = a1i + (double)B[i];
            C[9 + lane81] = a2ij + (double)B[9 + lane81] + a1i * b1j;
            #pragma unroll
            for (int k = 0; k < 9; ++k) {
                C[90 + lane81 * 9 + k] =
                    (double)A[90 + lane81 * 9 + k] + (double)B[90 + lane81 * 9 + k]
                    + a1i * (double)B[9 + j * 9 + k] + a2ij * (double)B[k];
            }
        }
    }
    __syncthreads();

    // ---- levels 1..5 in double, ping-pong slots (out: 32,48,56,60,62)
    int inoff = 0, outoff = 32;
    for (int m = 16; m >= 1; m >>= 1) {
        if (grp < 12) {
            for (int q = grp; q < m; q += 12) {
                const double* A = dbuf + (long)(inoff + 2 * q)     * SIGLEN;
                const double* B = dbuf + (long)(inoff + 2 * q + 1) * SIGLEN;
                double*       C = dbuf + (long)(outoff + q)        * SIGLEN;
                double a1i  = A[i];
                double b1j  = B[j];
                double a2ij = A[9 + lane81];
                if (j == 0) C[i] = a1i + B[i];
                C[9 + lane81] = a2ij + B[9 + lane81] + a1i * b1j;
                #pragma unroll
                for (int k = 0; k < 9; ++k) {
                    C[90 + lane81 * 9 + k] =
                        A[90 + lane81 * 9 + k] + B[90 + lane81 * 9 + k]
                        + a1i * B[9 + j * 9 + k] + a2ij * B[k];
                }
            }
        }
        __syncthreads();
        inoff = outoff;
        outoff += m;
    }

    // ---- log3 of total signature (slot 62), write flat (fp32)
    const double* S = dbuf + (long)62 * SIGLEN;
    if (tid < 81) {
        double s1i = S[i], s1j = S[j];
        if (j == 0) flat_sh[i] = (float)s1i;
        double s2ij = S[9 + lane81];
        flat_sh[9 + lane81] = (float)(s2ij - 0.5 * s1i * s1j);
        #pragma unroll
        for (int k = 0; k < 9; ++k) {
            double s1k = S[k];
            double l3 = S[90 + lane81 * 9 + k]
                      - 0.5 * (s1i * S[9 + j * 9 + k] + s2ij * s1k)
                      + s1i * s1j * s1k * (1.0 / 3.0);
            flat_sh[90 + lane81 * 9 + k] = (float)l3;
        }
    }
    __syncthreads();

    // ---- MLP layer 1: h = relu(flat @ W1 + b1). 512 threads:
    // 8 m-slices x 64 j-groups of 4 columns (float4 loads from W1).
    if (tid < 512) {
        const int slice = tid >> 6;   // 0..7
        const int jg    = tid & 63;   // 0..63
        float4 acc = make_float4(0.f, 0.f, 0.f, 0.f);
        #pragma unroll 4
        for (int m = slice; m < SIGLEN; m += 8) {
            float fm = flat_sh[m];
            float4 w = *reinterpret_cast<const float4*>(W1 + (long)m * HID + jg * 4);
            acc.x = fmaf(fm, w.x, acc.x);
            acc.y = fmaf(fm, w.y, acc.y);
            acc.z = fmaf(fm, w.z, acc.z);
            acc.w = fmaf(fm, w.w, acc.w);
        }
        *reinterpret_cast<float4*>(&hred[slice][jg * 4]) = acc;
    }
    __syncthreads();

    // ---- MLP layer 2: out = relu(h) @ W2 + b2 (block reduction)
    if (tid < HID) {
        float h = b1v[tid];
        #pragma unroll
        for (int s = 0; s < 8; ++s) h += hred[s][tid];
        h = fmaxf(h, 0.0f);
        float p = h * W2[tid];
        #pragma unroll
        for (int off = 16; off > 0; off >>= 1)
            p += __shfl_down_sync(0xffffffff, p, off);
        if ((tid & 31) == 0) osum[tid >> 5] = p;
    }
    __syncthreads();
    if (tid == 0) {
        float s = b2v[0];
        #pragma unroll
        for (int w = 0; w < 8; ++w) s += osum[w];
        out[b] = s;
    }
}

// =====================================================================
extern "C" void kernel_launch(void* const* d_in, const int* in_sizes, int n_in,
                              void* d_out, int out_size)
{
    const float* x  = (const float*)d_in[0];
    const float* W1 = (const float*)d_in[1];
    const float* b1 = (const float*)d_in[2];
    const float* W2 = (const float*)d_in[3];
    const float* b2 = (const float*)d_in[4];

    sig_partial_kernel<<<dim3(GRANGES, BATCH), 96>>>(x);
    combine_mlp_kernel<<<BATCH, 1024>>>(W1, b1, W2, b2, (float*)d_out);
}

// round 4
// speedup vs baseline: 1.4275x; 1.4275x over previous
#include <cuda_runtime.h>
#include <cstdint>

// ---------------- problem constants ----------------
#define BATCH    16
#define TSEQ     16384
#define CIN      8
#define GRANGES  64          // ranges per batch
#define LSTEPS   256         // TSEQ / GRANGES, multiple of CHUNK=32
#define SIGLEN   819         // 9 + 81 + 729
#define HID      256
#define SUBT     8           // subtrees per batch
#define RPS      8           // ranges per subtree

// ---------------- scratch (no allocations allowed) ----------------
__device__ float  g_part[BATCH * GRANGES * SIGLEN];     // fp32 range signatures
__device__ float2 g_sub [BATCH * SUBT    * SIGLEN];     // df64 subtree signatures

// ---------------- float-float (df64) helpers --------------------------
struct df2 { float hi, lo; };

__device__ __forceinline__ df2 df_add(df2 a, float b) {
    // Knuth two-sum (adds/subs only; nvcc does not reassociate fp)
    float s = __fadd_rn(a.hi, b);
    float v = __fsub_rn(s, a.hi);
    float e = __fadd_rn(__fsub_rn(a.hi, __fsub_rn(s, v)), __fsub_rn(b, v));
    e = __fadd_rn(e, a.lo);
    float hi = __fadd_rn(s, e);
    float lo = __fsub_rn(e, __fsub_rn(hi, s));
    df2 r; r.hi = hi; r.lo = lo; return r;
}

__device__ __forceinline__ df2 df_fmaf(df2 a, df2 p, float q) {
    // a += p*q  (p df64, q fp32)
    float ph = __fmul_rn(p.hi, q);
    float pl = __fmaf_rn(p.hi, q, -ph);
    pl = __fmaf_rn(p.lo, q, pl);
    df2 r = df_add(a, ph);
    r.lo = __fadd_rn(r.lo, pl);
    float hi = __fadd_rn(r.hi, r.lo);
    r.lo = __fsub_rn(r.lo, __fsub_rn(hi, r.hi));
    r.hi = hi;
    return r;
}

// =====================================================================
// Kernel 1: per-range truncated signature (levels 1..3), fp32.
// Grid (GRANGES, BATCH), 96 threads (81 active in main loop).
// Thread (i,j) owns S2[i][j] and S3[i][j][0..8]; S1[i] kept privately.
// Folded Chen step:  S3[ijk] += (S2ij + 0.5*(S1i + di/3)*dj) * dk
//                    S2ij    += (S1i + 0.5*di) * dj ;  S1i += di
// k-loop packed as fma.rn.f32x2 (4 packed lanes + 1 scalar for k=8).
// =====================================================================
__global__ __launch_bounds__(96)
void sig_partial_kernel(const float* __restrict__ x)
{
    __shared__ __align__(16) float ds[LSTEPS * 8];   // increments, 8 spatial channels

    const int b = blockIdx.y;
    const int g = blockIdx.x;
    const int tid = threadIdx.x;
    const float DT = 1.0f / 32.0f;

    // stage increments (chunk-aligned ranges: first step of each 32-chunk
    // jumps from the zero basepoint, so prev = 0 there)
    const long base = ((long)b * TSEQ + (long)g * LSTEPS) * CIN;
    for (int idx = tid; idx < LSTEPS * 8; idx += 96) {
        int s = idx >> 3, c = idx & 7;
        float cur  = x[base + (long)s * CIN + c];
        float prev = (s & 31) ? x[base + (long)(s - 1) * CIN + c] : 0.0f;
        ds[idx] = cur - prev;
    }
    __syncthreads();

    if (tid < 81) {
        const int i = tid / 9;
        const int j = tid % 9;
        float s1i = 0.0f, s2 = 0.0f;
        uint64_t s3p[4];
        #pragma unroll
        for (int k = 0; k < 4; ++k) s3p[k] = 0ull;
        float s38 = 0.0f;

        const float* dp = ds;
        #pragma unroll 2
        for (int s = 0; s < LSTEPS; ++s, dp += 8) {
            float di = (i < 8) ? dp[i] : DT;
            float dj = (j < 8) ? dp[j] : DT;
            const ulonglong2* q = reinterpret_cast<const ulonglong2*>(dp);
            ulonglong2 dl = q[0];     // packed (d0,d1),(d2,d3)
            ulonglong2 dh = q[1];     // packed (d4,d5),(d6,d7)

            float a = fmaf(fmaf(di, (1.0f / 3.0f), s1i), 0.5f * dj, s2);
            uint64_t ap;
            asm("mov.b64 %0, {%1, %2};" : "=l"(ap) : "f"(a), "f"(a));
            asm("fma.rn.f32x2 %0, %1, %2, %3;" : "=l"(s3p[0]) : "l"(ap), "l"(dl.x), "l"(s3p[0]));
            asm("fma.rn.f32x2 %0, %1, %2, %3;" : "=l"(s3p[1]) : "l"(ap), "l"(dl.y), "l"(s3p[1]));
            asm("fma.rn.f32x2 %0, %1, %2, %3;" : "=l"(s3p[2]) : "l"(ap), "l"(dh.x), "l"(s3p[2]));
            asm("fma.rn.f32x2 %0, %1, %2, %3;" : "=l"(s3p[3]) : "l"(ap), "l"(dh.y), "l"(s3p[3]));
            s38 = fmaf(a, DT, s38);

            s2  = fmaf(fmaf(di, 0.5f, s1i), dj, s2);
            s1i += di;
        }

        float* out = g_part + (long)(b * GRANGES + g) * SIGLEN;
        if (j == 0) out[i] = s1i;
        out[9 + tid] = s2;
        float* o3 = out + 90 + tid * 9;
        #pragma unroll
        for (int k = 0; k < 4; ++k) {
            float lo, hi;
            asm("mov.b64 {%0, %1}, %2;" : "=f"(lo), "=f"(hi) : "l"(s3p[k]));
            o3[2 * k]     = lo;
            o3[2 * k + 1] = hi;
        }
        o3[8] = s38;
    }
}

// =====================================================================
// Launch A: fold 8 consecutive range signatures into one subtree sig,
// df64 accumulators in shared. Grid (SUBT, BATCH), 768 threads.
// Group product: c1=a1+b1 ; c2=a2+b2+a1⊗b1 ; c3=a3+b3+a1⊗b2+a2⊗b1
// (a = earlier/left operand; tensor product is non-commutative)
// =====================================================================
__global__ __launch_bounds__(768)
void combine8_kernel()
{
    __shared__ float acc_hi[SIGLEN];
    __shared__ float acc_lo[SIGLEN];

    const int b = blockIdx.y;
    const int s = blockIdx.x;
    const int t = threadIdx.x;
    const bool act = t < 729;
    const int i = t / 81;
    const int j = (t / 9) % 9;
    const int k = t % 9;

    const float* base = g_part + (long)(b * GRANGES + s * RPS) * SIGLEN;

    // init acc = range 0 of this subtree
    for (int idx = t; idx < SIGLEN; idx += 768) {
        acc_hi[idx] = base[idx];
        acc_lo[idx] = 0.0f;
    }
    __syncthreads();

    for (int p = 1; p < RPS; ++p) {
        const float* B = base + (long)p * SIGLEN;
        df2 c3n, c2n, c1n;
        if (act) {
            float b1k  = B[k];
            float b2jk = B[9 + j * 9 + k];
            float b3   = B[90 + t];

            df2 a1i  = { acc_hi[i],              acc_lo[i] };
            df2 a2ij = { acc_hi[9 + i * 9 + j],  acc_lo[9 + i * 9 + j] };
            df2 c3   = { acc_hi[90 + t],         acc_lo[90 + t] };
            c3 = df_add(c3, b3);
            c3 = df_fmaf(c3, a1i, b2jk);
            c3 = df_fmaf(c3, a2ij, b1k);
            c3n = c3;

            if (t < 81) {   // level-2 elem (i2=t/9, j2=t%9): b2jk==B[9+t], b1k==B[j2]
                df2 a1s = { acc_hi[t / 9], acc_lo[t / 9] };
                df2 c2  = { acc_hi[9 + t], acc_lo[9 + t] };
                c2 = df_add(c2, b2jk);
                c2 = df_fmaf(c2, a1s, b1k);
                c2n = c2;
            }
            if (t < 9) {    // level-1: k==t so b1k==B[t]
                df2 c1 = { acc_hi[t], acc_lo[t] };
                c1n = df_add(c1, b1k);
            }
        }
        __syncthreads();
        if (act) {
            acc_hi[90 + t] = c3n.hi;  acc_lo[90 + t] = c3n.lo;
            if (t < 81) { acc_hi[9 + t] = c2n.hi;  acc_lo[9 + t] = c2n.lo; }
            if (t < 9)  { acc_hi[t]     = c1n.hi;  acc_lo[t]     = c1n.lo; }
        }
        __syncthreads();
    }

    float2* out = g_sub + (long)(b * SUBT + s) * SIGLEN;
    for (int idx = t; idx < SIGLEN; idx += 768)
        out[idx] = make_float2(acc_hi[idx], acc_lo[idx]);
}

// =====================================================================
// Launch B: per-batch fold of 8 subtree sigs (fp64, tiny), log3, MLP.
// Grid BATCH, 768 threads.
// =====================================================================
__global__ __launch_bounds__(768)
void final_kernel(const float* __restrict__ W1, const float* __restrict__ b1v,
                  const float* __restrict__ W2, const float* __restrict__ b2v,
                  float* __restrict__ out)
{
    __shared__ double accd[SIGLEN];
    __shared__ float  flat_sh[SIGLEN];
    __shared__ __align__(16) float hred[8][HID];
    __shared__ float osum[8];

    const int b = blockIdx.x;
    const int t = threadIdx.x;
    const bool act = t < 729;
    const int i = t / 81;
    const int j = (t / 9) % 9;
    const int k = t % 9;

    const float2* sub = g_sub + (long)(b * SUBT) * SIGLEN;

    for (int idx = t; idx < SIGLEN; idx += 768) {
        float2 v = sub[idx];
        accd[idx] = (double)v.x + (double)v.y;
    }
    __syncthreads();

    for (int p = 1; p < SUBT; ++p) {
        const float2* B = sub + (long)p * SIGLEN;
        double c3n = 0.0, c2n = 0.0, c1n = 0.0;
        if (act) {
            float2 v;
            v = B[k];              double b1k  = (double)v.x + (double)v.y;
            v = B[9 + j * 9 + k];  double b2jk = (double)v.x + (double)v.y;
            v = B[90 + t];         double b3   = (double)v.x + (double)v.y;

            double a1i  = accd[i];
            double a2ij = accd[9 + i * 9 + j];
            c3n = accd[90 + t] + b3 + a1i * b2jk + a2ij * b1k;
            if (t < 81) c2n = accd[9 + t] + b2jk + accd[t / 9] * b1k;
            if (t < 9)  c1n = accd[t] + b1k;
        }
        __syncthreads();
        if (act) {
            accd[90 + t] = c3n;
            if (t < 81) accd[9 + t] = c2n;
            if (t < 9)  accd[t]     = c1n;
        }
        __syncthreads();
    }

    // ---- log3 -> flat (fp32) ----
    if (act) {
        double s1i = accd[i], s1j = accd[j], s1k = accd[k];
        double l3 = accd[90 + t]
                  - 0.5 * (s1i * accd[9 + j * 9 + k] + accd[9 + i * 9 + j] * s1k)
                  + s1i * s1j * s1k * (1.0 / 3.0);
        flat_sh[90 + t] = (float)l3;
        if (t < 81) flat_sh[9 + t] = (float)(accd[9 + t] - 0.5 * accd[t / 9] * accd[t % 9]);
        if (t < 9)  flat_sh[t] = (float)accd[t];
    }
    __syncthreads();

    // ---- MLP layer 1: h = relu(flat @ W1 + b1) ----
    if (t < 512) {
        const int slice = t >> 6;   // 0..7
        const int jg    = t & 63;   // 0..63
        float4 acc = make_float4(0.f, 0.f, 0.f, 0.f);
        #pragma unroll 4
        for (int m = slice; m < SIGLEN; m += 8) {
            float fm = flat_sh[m];
            float4 w = *reinterpret_cast<const float4*>(W1 + (long)m * HID + jg * 4);
            acc.x = fmaf(fm, w.x, acc.x);
            acc.y = fmaf(fm, w.y, acc.y);
            acc.z = fmaf(fm, w.z, acc.z);
            acc.w = fmaf(fm, w.w, acc.w);
        }
        *reinterpret_cast<float4*>(&hred[slice][jg * 4]) = acc;
    }
    __syncthreads();

    // ---- MLP layer 2 ----
    if (t < HID) {
        float h = b1v[t];
        #pragma unroll
        for (int s = 0; s < 8; ++s) h += hred[s][t];
        h = fmaxf(h, 0.0f);
        float p = h * W2[t];
        #pragma unroll
        for (int off = 16; off > 0; off >>= 1)
            p += __shfl_down_sync(0xffffffff, p, off);
        if ((t & 31) == 0) osum[t >> 5] = p;
    }
    __syncthreads();
    if (t == 0) {
        float s = b2v[0];
        #pragma unroll
        for (int w = 0; w < 8; ++w) s += osum[w];
        out[b] = s;
    }
}

// =====================================================================
extern "C" void kernel_launch(void* const* d_in, const int* in_sizes, int n_in,
                              void* d_out, int out_size)
{
    const float* x  = (const float*)d_in[0];
    const float* W1 = (const float*)d_in[1];
    const float* b1 = (const float*)d_in[2];
    const float* W2 = (const float*)d_in[3];
    const float* b2 = (const float*)d_in[4];

    sig_partial_kernel<<<dim3(GRANGES, BATCH), 96>>>(x);
    combine8_kernel<<<dim3(SUBT, BATCH), 768>>>();
    final_kernel<<<BATCH, 768>>>(W1, b1, W2, b2, (float*)d_out);
}

// round 6
// speedup vs baseline: 1.4798x; 1.0366x over previous
#include <cuda_runtime.h>
#include <cstdint>

// ---------------- problem constants ----------------
#define BATCH    16
#define TSEQ     16384
#define CIN      8
#define GRANGES  128         // ranges per batch
#define LSTEPS   128         // TSEQ / GRANGES, multiple of CHUNK=32
#define SIGLEN   819         // 9 + 81 + 729
#define HID      256
#define SUBT     16          // subtrees per batch
#define RPS      8           // ranges per subtree
#define TSTRIDE  132         // channel-major row stride (floats): 16B-aligned, bank-spread

// ---------------- scratch (no allocations allowed) ----------------
__device__ float  g_part[BATCH * GRANGES * SIGLEN];     // fp32 range signatures
__device__ float2 g_sub [BATCH * SUBT    * SIGLEN];     // df64 subtree signatures

// ---------------- float-float (df64) helpers --------------------------
struct df2 { float hi, lo; };

__device__ __forceinline__ df2 df_add(df2 a, float b) {
    float s = __fadd_rn(a.hi, b);
    float v = __fsub_rn(s, a.hi);
    float e = __fadd_rn(__fsub_rn(a.hi, __fsub_rn(s, v)), __fsub_rn(b, v));
    e = __fadd_rn(e, a.lo);
    float hi = __fadd_rn(s, e);
    float lo = __fsub_rn(e, __fsub_rn(hi, s));
    df2 r; r.hi = hi; r.lo = lo; return r;
}

__device__ __forceinline__ df2 df_fmaf(df2 a, df2 p, float q) {
    // a += p*q  (p df64, q fp32)
    float ph = __fmul_rn(p.hi, q);
    float pl = __fmaf_rn(p.hi, q, -ph);
    pl = __fmaf_rn(p.lo, q, pl);
    df2 r = df_add(a, ph);
    r.lo = __fadd_rn(r.lo, pl);
    float hi = __fadd_rn(r.hi, r.lo);
    r.lo = __fsub_rn(r.lo, __fsub_rn(hi, r.hi));
    r.hi = hi;
    return r;
}

// =====================================================================
// Kernel 1: per-range truncated signature (levels 1..3), fp32.
// Grid (GRANGES, BATCH), 96 threads (81 active in main loop).
// Thread (i,j) owns S2[i][j] and S3[i][j][0..8]; S1[i] kept privately.
// Folded Chen step:  S3[ijk] += (S2ij + 0.5*(S1i + di/3)*dj) * dk
//                    S2ij    += (S1i + 0.5*di) * dj ;  S1i += di
// k-loop packed as fma.rn.f32x2; di/dj fetched 4 steps at a time from a
// channel-major shared copy (compile-time component selects under unroll).
// =====================================================================
__global__ __launch_bounds__(96)
void sig_partial_kernel(const float* __restrict__ x)
{
    __shared__ __align__(16) float ds [LSTEPS * 8];      // step-major (for packed k-vector)
    __shared__ __align__(16) float dst[8 * TSTRIDE];     // channel-major (for di/dj)

    const int b = blockIdx.y;
    const int g = blockIdx.x;
    const int tid = threadIdx.x;
    const float DT = 1.0f / 32.0f;

    // stage increments (chunk-aligned ranges: first step of each 32-chunk
    // jumps from the zero basepoint, so prev = 0 there)
    const long base = ((long)b * TSEQ + (long)g * LSTEPS) * CIN;
    for (int idx = tid; idx < LSTEPS * 8; idx += 96) {
        int s = idx >> 3, c = idx & 7;
        float cur  = x[base + (long)s * CIN + c];
        float prev = (s & 31) ? x[base + (long)(s - 1) * CIN + c] : 0.0f;
        ds[idx] = cur - prev;
        dst[c * TSTRIDE + s] = cur - prev;
    }
    __syncthreads();

    if (tid < 81) {
        const int i = tid / 9;
        const int j = tid % 9;
        float s1i = 0.0f, s2 = 0.0f;
        uint64_t s3p[4];
        #pragma unroll
        for (int k = 0; k < 4; ++k) s3p[k] = 0ull;
        float s38 = 0.0f;
        const float4 DT4 = make_float4(DT, DT, DT, DT);

        #pragma unroll 1
        for (int s0 = 0; s0 < LSTEPS; s0 += 4) {
            float4 di4 = (i < 8) ? *reinterpret_cast<const float4*>(&dst[i * TSTRIDE + s0]) : DT4;
            float4 dj4 = (j < 8) ? *reinterpret_cast<const float4*>(&dst[j * TSTRIDE + s0]) : DT4;
            const float* dp = ds + s0 * 8;

            #pragma unroll
            for (int u = 0; u < 4; ++u, dp += 8) {
                float di = (u == 0) ? di4.x : (u == 1) ? di4.y : (u == 2) ? di4.z : di4.w;
                float dj = (u == 0) ? dj4.x : (u == 1) ? dj4.y : (u == 2) ? dj4.z : dj4.w;
                const ulonglong2* q = reinterpret_cast<const ulonglong2*>(dp);
                ulonglong2 dl = q[0];     // packed (d0,d1),(d2,d3)
                ulonglong2 dh = q[1];     // packed (d4,d5),(d6,d7)

                float a = fmaf(fmaf(di, (1.0f / 3.0f), s1i), 0.5f * dj, s2);
                uint64_t ap;
                asm("mov.b64 %0, {%1, %2};" : "=l"(ap) : "f"(a), "f"(a));
                asm("fma.rn.f32x2 %0, %1, %2, %3;" : "=l"(s3p[0]) : "l"(ap), "l"(dl.x), "l"(s3p[0]));
                asm("fma.rn.f32x2 %0, %1, %2, %3;" : "=l"(s3p[1]) : "l"(ap), "l"(dl.y), "l"(s3p[1]));
                asm("fma.rn.f32x2 %0, %1, %2, %3;" : "=l"(s3p[2]) : "l"(ap), "l"(dh.x), "l"(s3p[2]));
                asm("fma.rn.f32x2 %0, %1, %2, %3;" : "=l"(s3p[3]) : "l"(ap), "l"(dh.y), "l"(s3p[3]));
                s38 = fmaf(a, DT, s38);

                s2  = fmaf(fmaf(di, 0.5f, s1i), dj, s2);
                s1i += di;
            }
        }

        float* out = g_part + (long)(b * GRANGES + g) * SIGLEN;
        if (j == 0) out[i] = s1i;
        out[9 + tid] = s2;
        float* o3 = out + 90 + tid * 9;
        #pragma unroll
        for (int k = 0; k < 4; ++k) {
            float lo, hi;
            asm("mov.b64 {%0, %1}, %2;" : "=f"(lo), "=f"(hi) : "l"(s3p[k]));
            o3[2 * k]     = lo;
            o3[2 * k + 1] = hi;
        }
        o3[8] = s38;
    }
}

// =====================================================================
// Launch A: fold RPS consecutive range signatures into one subtree sig.
// Level-3 df64 accumulator lives in registers (exclusively owned per
// thread); only levels 1+2 go through ping-pong shared (1 sync / fold).
// Group product: c1=a1+b1 ; c2=a2+b2+a1⊗b1 ; c3=a3+b3+a1⊗b2+a2⊗b1
// (a = earlier/left operand; tensor product is non-commutative)
// Grid (SUBT, BATCH), 768 threads (729 active).
// =====================================================================
__global__ __launch_bounds__(768)
void combine8_kernel()
{
    __shared__ float s1h[2][9],  s1l[2][9];
    __shared__ float s2h[2][81], s2l[2][81];

    const int b = blockIdx.y;
    const int s = blockIdx.x;
    const int t = threadIdx.x;
    const bool act = t < 729;
    const int i = t / 81;
    const int j = (t / 9) % 9;
    const int k = t % 9;

    const float* base = g_part + (long)(b * GRANGES + s * RPS) * SIGLEN;

    df2 c3 = { 0.f, 0.f };
    if (act) {
        c3.hi = base[90 + t];
        if (t < 81) { s2h[0][t] = base[9 + t]; s2l[0][t] = 0.f; }
        if (t < 9)  { s1h[0][t] = base[t];     s1l[0][t] = 0.f; }
    }
    __syncthreads();

    int cur = 0;
    for (int p = 1; p < RPS; ++p) {
        const float* B = base + (long)p * SIGLEN;
        if (act) {
            float b1k  = B[k];
            float b2jk = B[9 + j * 9 + k];
            float b3   = B[90 + t];

            df2 a1i  = { s1h[cur][i],         s1l[cur][i] };
            df2 a2ij = { s2h[cur][i * 9 + j], s2l[cur][i * 9 + j] };
            c3 = df_add(c3, b3);
            c3 = df_fmaf(c3, a1i, b2jk);
            c3 = df_fmaf(c3, a2ij, b1k);

            if (t < 81) {   // element (i2=t/9, j2=t%9): b2jk==B[9+t], b1k==B[t%9]
                df2 a1s = { s1h[cur][t / 9], s1l[cur][t / 9] };
                df2 c2  = { s2h[cur][t],     s2l[cur][t] };
                c2 = df_add(c2, b2jk);
                c2 = df_fmaf(c2, a1s, b1k);
                s2h[cur ^ 1][t] = c2.hi;  s2l[cur ^ 1][t] = c2.lo;
            }
            if (t < 9) {    // level-1: k==t so b1k==B[t]
                df2 c1 = { s1h[cur][t], s1l[cur][t] };
                c1 = df_add(c1, b1k);
                s1h[cur ^ 1][t] = c1.hi;  s1l[cur ^ 1][t] = c1.lo;
            }
        }
        __syncthreads();
        cur ^= 1;
    }

    float2* out = g_sub + (long)(b * SUBT + s) * SIGLEN;
    if (act) {
        out[90 + t] = make_float2(c3.hi, c3.lo);
        if (t < 81) out[9 + t] = make_float2(s2h[cur][t], s2l[cur][t]);
        if (t < 9)  out[t]     = make_float2(s1h[cur][t], s1l[cur][t]);
    }
}

// =====================================================================
// Launch B: per-batch fold of SUBT subtree sigs (fp64; level-3 in regs,
// 1 sync/fold), log3, MLP.  Grid BATCH, 768 threads.
// =====================================================================
__global__ __launch_bounds__(768)
void final_kernel(const float* __restrict__ W1, const float* __restrict__ b1v,
                  const float* __restrict__ W2, const float* __restrict__ b2v,
                  float* __restrict__ out)
{
    __shared__ double s1d[2][9], s2d[2][81];
    __shared__ float  flat_sh[SIGLEN];
    __shared__ __align__(16) float hred[8][HID];
    __shared__ float osum[8];

    const int b = blockIdx.x;
    const int t = threadIdx.x;
    const bool act = t < 729;
    const int i = t / 81;
    const int j = (t / 9) % 9;
    const int k = t % 9;

    const float2* sub = g_sub + (long)(b * SUBT) * SIGLEN;

    double c3 = 0.0;
    if (act) {
        float2 v = sub[90 + t];
        c3 = (double)v.x + (double)v.y;
        if (t < 81) { float2 w = sub[9 + t]; s2d[0][t] = (double)w.x + (double)w.y; }
        if (t < 9)  { float2 w = sub[t];     s1d[0][t] = (double)w.x + (double)w.y; }
    }
    __syncthreads();

    int cur = 0;
    for (int p = 1; p < SUBT; ++p) {
        const float2* B = sub + (long)p * SIGLEN;
        if (act) {
            float2 v;
            v = B[k];              double b1k  = (double)v.x + (double)v.y;
            v = B[9 + j * 9 + k];  double b2jk = (double)v.x + (double)v.y;
            v = B[90 + t];         double b3   = (double)v.x + (double)v.y;

            c3 = c3 + b3 + s1d[cur][i] * b2jk + s2d[cur][i * 9 + j] * b1k;
            if (t < 81) s2d[cur ^ 1][t] = s2d[cur][t] + b2jk + s1d[cur][t / 9] * b1k;
            if (t < 9)  s1d[cur ^ 1][t] = s1d[cur][t] + b1k;
        }
        __syncthreads();
        cur ^= 1;
    }

    // ---- log3 -> flat (fp32) ----
    if (act) {
        double s1i = s1d[cur][i], s1j = s1d[cur][j], s1k = s1d[cur][k];
        double l3 = c3
                  - 0.5 * (s1i * s2d[cur][j * 9 + k] + s2d[cur][i * 9 + j] * s1k)
                  + s1i * s1j * s1k * (1.0 / 3.0);
        flat_sh[90 + t] = (float)l3;
        if (t < 81) flat_sh[9 + t] = (float)(s2d[cur][t] - 0.5 * s1d[cur][t / 9] * s1d[cur][t % 9]);
        if (t < 9)  flat_sh[t] = (float)s1d[cur][t];
    }
    __syncthreads();

    // ---- MLP layer 1: h = relu(flat @ W1 + b1) ----
    if (t < 512) {
        const int slice = t >> 6;   // 0..7
        const int jg    = t & 63;   // 0..63
        float4 acc = make_float4(0.f, 0.f, 0.f, 0.f);
        #pragma unroll 4
        for (int m = slice; m < SIGLEN; m += 8) {
            float fm = flat_sh[m];
            float4 w = *reinterpret_cast<const float4*>(W1 + (long)m * HID + jg * 4);
            acc.x = fmaf(fm, w.x, acc.x);
            acc.y = fmaf(fm, w.y, acc.y);
            acc.z = fmaf(fm, w.z, acc.z);
            acc.w = fmaf(fm, w.w, acc.w);
        }
        *reinterpret_cast<float4*>(&hred[slice][jg * 4]) = acc;
    }
    __syncthreads();

    // ---- MLP layer 2 ----
    if (t < HID) {
        float h = b1v[t];
        #pragma unroll
        for (int s = 0; s < 8; ++s) h += hred[s][t];
        h = fmaxf(h, 0.0f);
        float p = h * W2[t];
        #pragma unroll
        for (int off = 16; off > 0; off >>= 1)
            p += __shfl_down_sync(0xffffffff, p, off);
        if ((t & 31) == 0) osum[t >> 5] = p;
    }
    __syncthreads();
    if (t == 0) {
        float s = b2v[0];
        #pragma unroll
        for (int w = 0; w < 8; ++w) s += osum[w];
        out[b] = s;
    }
}

// =====================================================================
extern "C" void kernel_launch(void* const* d_in, const int* in_sizes, int n_in,
                              void* d_out, int out_size)
{
    const float* x  = (const float*)d_in[0];
    const float* W1 = (const float*)d_in[1];
    const float* b1 = (const float*)d_in[2];
    const float* W2 = (const float*)d_in[3];
    const float* b2 = (const float*)d_in[4];

    sig_partial_kernel<<<dim3(GRANGES, BATCH), 96>>>(x);
    combine8_kernel<<<dim3(SUBT, BATCH), 768>>>();
    final_kernel<<<BATCH, 768>>>(W1, b1, W2, b2, (float*)d_out);
}